// round 16
// baseline (speedup 1.0000x reference)
#include <cuda_runtime.h>
#include <math.h>
#include <float.h>
#include <stdint.h>

// ---------------- problem constants ----------------
#define BEAM   5
#define TOPK   5
#define VOCAB  128000
#define HIST   511
#define NUM_KV 16
#define HEADS  8
#define SEQ    2048
#define HDIM   128

#define SM_CHUNKS 125
#define TPB_SM    256
#define NWARPS_B  (SM_CHUNKS*8)

#define NEG_SENTINEL (-FLT_MAX)

#define KV_ROW_ELEMS  (HEADS*SEQ*HDIM)          // 2,097,152 floats per (kv,beam)
#define KV_ROW4       (KV_ROW_ELEMS/4)
#define KV_ROW_BYTES  (KV_ROW_ELEMS*4)          // 8 MB
#define KV_TOTAL      (NUM_KV*BEAM*KV_ROW_ELEMS)

// output layout (floats), reference tuple order
#define OFF_SAVE   (KV_TOTAL)
#define OFF_RP     (OFF_SAVE + BEAM*(HIST+1))
#define OFF_PROB   (OFF_RP + BEAM*VOCAB)
#define OFF_TOK    (OFF_PROB + BEAM)
#define OFF_MAXIDX (OFF_TOK + BEAM)

// ---------------- device scratch ----------------
__device__ float g_wm[BEAM*NWARPS_B];
__device__ float g_ws[BEAM*NWARPS_B];
__device__ int   g_beam_index[BEAM];
__device__ int   g_token[BEAM];
__device__ unsigned int g_counter = 0;

// ---------------- top-5 helpers ----------------
__device__ __forceinline__ void top5_insert(float* v, int* ix, float val, int idx) {
    if (val < v[TOPK-1]) return;
    if (val == v[TOPK-1] && idx >= ix[TOPK-1]) return;
    int p = TOPK - 1;
    #pragma unroll
    for (int q = TOPK - 1; q > 0; q--) {
        if (val > v[q-1] || (val == v[q-1] && idx < ix[q-1])) {
            v[q] = v[q-1]; ix[q] = ix[q-1]; p = q - 1;
        } else break;
    }
    v[p] = val; ix[p] = idx;
}

__device__ __forceinline__ void warp_merge(float* v, int* ix, float& m, float& s) {
    #pragma unroll
    for (int off = 16; off > 0; off >>= 1) {
        float pv[TOPK]; int pi[TOPK];
        #pragma unroll
        for (int j = 0; j < TOPK; j++) {
            pv[j] = __shfl_down_sync(0xffffffffu, v[j],  off);
            pi[j] = __shfl_down_sync(0xffffffffu, ix[j], off);
        }
        float pm = __shfl_down_sync(0xffffffffu, m, off);
        float ps = __shfl_down_sync(0xffffffffu, s, off);
        #pragma unroll
        for (int j = 0; j < TOPK; j++) top5_insert(v, ix, pv[j], pi[j]);
        float nm = fmaxf(m, pm);
        s = s * __expf(m - nm) + ps * __expf(pm - nm);
        m = nm;
    }
}

// ---------------- kernel 1: softmax/topk (R14, unchanged) ----------------
__global__ void __launch_bounds__(TPB_SM)
softmax_topk_kernel(const float4* __restrict__ logits, const float4* __restrict__ rpen,
                    const float* __restrict__ prev_prob,
                    float* __restrict__ out_prob,
                    float* __restrict__ out_tok,
                    float* __restrict__ out_maxidx) {
    const int c = blockIdx.x;
    const int b = blockIdx.y;
    const int t = threadIdx.x;
    const int warp = t >> 5;
    const int lane = t & 31;

    const int f4i = c * TPB_SM + t;
    float4 xl = __ldg(logits + (size_t)b * (VOCAB/4) + f4i);
    float4 xr = __ldg(rpen   + (size_t)b * (VOCAB/4) + f4i);
    float x0 = xl.x * xr.x, x1 = xl.y * xr.y, x2 = xl.z * xr.z, x3 = xl.w * xr.w;

    float m = fmaxf(fmaxf(x0, x1), fmaxf(x2, x3));
    float s = __expf(x0-m) + __expf(x1-m) + __expf(x2-m) + __expf(x3-m);

    #pragma unroll
    for (int off = 16; off > 0; off >>= 1) {
        float pm = __shfl_down_sync(0xffffffffu, m, off);
        float ps = __shfl_down_sync(0xffffffffu, s, off);
        float nm = fmaxf(m, pm);
        s = s * __expf(m - nm) + ps * __expf(pm - nm);
        m = nm;
    }
    if (lane == 0) {
        const int ws_idx = b * NWARPS_B + c * 8 + warp;
        g_wm[ws_idx] = m;
        g_ws[ws_idx] = s;
        __threadfence();
    }
    __syncthreads();

    __shared__ int s_last;
    if (t == 0) {
        unsigned int tk = atomicAdd(&g_counter, 1u);
        s_last = (tk == (unsigned)(SM_CHUNKS*BEAM - 1));
    }
    __syncthreads();
    if (!s_last) return;

    __shared__ float s_cur[BEAM*TOPK];
    __shared__ int   s_ctok[BEAM*TOPK];

    if (warp < BEAM) {
        const int bb = warp;
        float v[TOPK]; int ix[TOPK];
        #pragma unroll
        for (int j = 0; j < TOPK; j++) { v[j] = NEG_SENTINEL; ix[j] = 0x7FFFFFFF; }
        float cm = NEG_SENTINEL, cs = 0.0f;
        for (int i = lane; i < 1024; i += 32) {
            float pm = NEG_SENTINEL, ps = 0.0f;
            if (i < NWARPS_B) { pm = g_wm[bb*NWARPS_B + i]; ps = g_ws[bb*NWARPS_B + i]; }
            float nm = fmaxf(cm, pm);
            cs = cs * __expf(cm - nm) + ps * __expf(pm - nm);
            cm = nm;
            top5_insert(v, ix, pm, i);
        }
        warp_merge(v, ix, cm, cs);

        float lse = cm + logf(cs);
        lse = __shfl_sync(0xffffffffu, lse, 0);
        int slots[TOPK];
        #pragma unroll
        for (int j = 0; j < TOPK; j++) slots[j] = __shfl_sync(0xffffffffu, ix[j], 0);

        float tv[TOPK]; int ti[TOPK];
        #pragma unroll
        for (int j = 0; j < TOPK; j++) { tv[j] = NEG_SENTINEL; ti[j] = 0x7FFFFFFF; }
        #pragma unroll
        for (int j = 0; j < TOPK; j++) {
            const int ws = slots[j];
            const int f4 = ws * 32 + lane;
            float4 yl = __ldg(logits + (size_t)bb * (VOCAB/4) + f4);
            float4 yr = __ldg(rpen   + (size_t)bb * (VOCAB/4) + f4);
            const int e0 = f4 * 4;
            top5_insert(tv, ti, yl.x * yr.x, e0 + 0);
            top5_insert(tv, ti, yl.y * yr.y, e0 + 1);
            top5_insert(tv, ti, yl.z * yr.z, e0 + 2);
            top5_insert(tv, ti, yl.w * yr.w, e0 + 3);
        }
        float dm = NEG_SENTINEL, ds = 0.0f;
        warp_merge(tv, ti, dm, ds);

        if (lane == 0) {
            float pp = prev_prob[bb];
            #pragma unroll
            for (int j = 0; j < TOPK; j++) {
                s_cur[bb*TOPK + j]  = tv[j] - lse + pp;
                s_ctok[bb*TOPK + j] = ti[j];
            }
        }
    }
    __syncthreads();

    if (t == 0) {
        bool used[BEAM*TOPK];
        #pragma unroll
        for (int i = 0; i < BEAM*TOPK; i++) used[i] = false;
        for (int k = 0; k < BEAM; k++) {
            int best = 0; float bv = -INFINITY;
            for (int i = 0; i < BEAM*TOPK; i++) {
                if (!used[i] && s_cur[i] > bv) { bv = s_cur[i]; best = i; }
            }
            used[best] = true;
            int bi  = best / TOPK;
            int tok = s_ctok[best];
            g_beam_index[k] = bi;
            g_token[k]      = tok;
            out_prob[k]     = bv;
            out_tok[k]      = (float)tok;
            if (k == 0) out_maxidx[0] = (float)tok;
        }
        g_counter = 0;
        __threadfence();
    }
}

// ---------------- kernel 2: TMA bulk gather (R14 config, SEGS 16->8) ----------------
// Source-keyed rows (kv, si): reads = unique_beams * 128MB structurally.
// 3x64KB buffers, lookahead 2. SEGS=8: 384 active blocks x 16 iters (vs 768 x 8)
// -> half the pipeline-ramp overhead, fewer waves, same 128KB in flight per SM.
struct KvPtrs { const float4* p[NUM_KV]; };

#define TPB        128
#define CHUNK      65536
#define NBUF       3
#define SEGS       8                                // segments per (kv,si) row
#define SEG_BYTES  (KV_ROW_BYTES/SEGS)              // 1 MB
#define ITERS      (SEG_BYTES/CHUNK)                // 16 chunks per segment
#define KV_BLOCKS  (NUM_KV*BEAM*SEGS)               // 640
#define RP_F4      (BEAM*VOCAB/4)                   // 160000
#define RP_BLOCKS  160
#define RP_PER_BLK (RP_F4/RP_BLOCKS)                // 1000
#define TOTAL_BLKS (KV_BLOCKS + RP_BLOCKS + 1)      // 801
#define SMEM_BYTES (NBUF*CHUNK + 32)

__device__ __forceinline__ uint32_t smem_u32(const void* p) {
    uint32_t a;
    asm("{ .reg .u64 t; cvta.to.shared.u64 t, %1; cvt.u32.u64 %0, t; }" : "=r"(a) : "l"(p));
    return a;
}

__device__ __forceinline__ void mbar_wait(uint32_t mb, uint32_t parity) {
    uint32_t done;
    asm volatile(
        "{\n\t.reg .pred p;\n\t"
        "mbarrier.try_wait.parity.acquire.cta.shared::cta.b64 p, [%1], %2;\n\t"
        "selp.b32 %0, 1, 0, p;\n\t}"
        : "=r"(done) : "r"(mb), "r"(parity) : "memory");
    while (!done) {
        asm volatile(
            "{\n\t.reg .pred p;\n\t"
            "mbarrier.try_wait.parity.acquire.cta.shared::cta.b64 p, [%1], %2, 0x989680;\n\t"
            "selp.b32 %0, 1, 0, p;\n\t}"
            : "=r"(done) : "r"(mb), "r"(parity) : "memory");
    }
}

__device__ __forceinline__ void tma_load(uint32_t buf, const char* src, uint32_t mb) {
    asm volatile("mbarrier.arrive.expect_tx.shared.b64 _, [%0], %1;"
                 :: "r"(mb), "r"((uint32_t)CHUNK) : "memory");
    asm volatile(
        "cp.async.bulk.shared::cluster.global.mbarrier::complete_tx::bytes "
        "[%0], [%1], %2, [%3];"
        :: "r"(buf), "l"(src), "r"((uint32_t)CHUNK), "r"(mb) : "memory");
}

__global__ void __launch_bounds__(TPB)
gather_tma_kernel(KvPtrs kp,
                  const float* __restrict__ rpen,
                  const int*   __restrict__ save_id,
                  const float* __restrict__ pen,
                  float* __restrict__ out) {
    extern __shared__ char smem[];
    const int bid = blockIdx.x;

    if (bid < KV_BLOCKS) {
        if (threadIdx.x != 0) return;                // single-thread TMA driver

        const int row = bid / SEGS;                  // (kv, si)
        const int seg = bid - row * SEGS;
        const int kv  = row / BEAM;
        const int si  = row - kv * BEAM;

        int mask = 0;
        #pragma unroll
        for (int d = 0; d < BEAM; d++)
            if (g_beam_index[d] == si) mask |= (1 << d);
        if (mask == 0) return;                       // unused source: zero traffic

        const uint32_t buf0 = smem_u32(smem);
        const uint32_t mbar = buf0 + NBUF*CHUNK;

        #pragma unroll
        for (int i = 0; i < NBUF; i++)
            asm volatile("mbarrier.init.shared.b64 [%0], 1;" :: "r"(mbar + 8*i) : "memory");
        asm volatile("fence.proxy.async.shared::cta;" ::: "memory");

        const char* src = (const char*)kp.p[kv] + (size_t)si * KV_ROW_BYTES
                                                + (size_t)seg * SEG_BYTES;
        char* outb = (char*)out;
        uint32_t ph[NBUF];
        #pragma unroll
        for (int i = 0; i < NBUF; i++) ph[i] = 0;

        // prefetch loads 0,1 (lookahead 2)
        tma_load(buf0 + 0 * CHUNK, src + 0 * (size_t)CHUNK, mbar + 0);
        tma_load(buf0 + 1 * CHUNK, src + 1 * (size_t)CHUNK, mbar + 8);

        for (int c = 0; c < ITERS; c++) {
            const int i = c % NBUF;
            const uint32_t buf = buf0 + i * CHUNK;

            mbar_wait(mbar + 8*i, ph[i]);
            ph[i] ^= 1;

            #pragma unroll
            for (int d = 0; d < BEAM; d++) {
                if (mask & (1 << d)) {
                    char* dst = outb + ((size_t)kv * BEAM + d) * KV_ROW_BYTES
                                     + (size_t)seg * SEG_BYTES
                                     + (size_t)c * CHUNK;
                    asm volatile(
                        "cp.async.bulk.global.shared::cta.bulk_group [%0], [%1], %2;"
                        :: "l"(dst), "r"(buf), "r"((uint32_t)CHUNK) : "memory");
                }
            }
            asm volatile("cp.async.bulk.commit_group;" ::: "memory");

            const int n = c + 2;
            if (n < ITERS) {
                // store-group (c-1) must be done reading buf[n % NBUF]
                asm volatile("cp.async.bulk.wait_group.read 1;" ::: "memory");
                const int j = n % NBUF;
                tma_load(buf0 + j * CHUNK, src + (size_t)n * CHUNK, mbar + 8*j);
            }
        }
        asm volatile("cp.async.bulk.wait_group 0;" ::: "memory");
        return;
    }

    if (bid < KV_BLOCKS + RP_BLOCKS) {
        // ---- repeat_penalty gather (float4) + token penalty ----
        const int base = (bid - KV_BLOCKS) * RP_PER_BLK;
        for (int k = threadIdx.x; k < RP_PER_BLK; k += TPB) {
            int i  = base + k;
            int b  = i / (VOCAB/4);
            int v4 = i - b * (VOCAB/4);
            int bi = g_beam_index[b];
            float4 x = __ldcg((const float4*)rpen + (size_t)bi * (VOCAB/4) + v4);
            int tok = g_token[b];
            if ((tok >> 2) == v4) {
                float p = pen[0];
                ((float*)&x)[tok & 3] *= p;
            }
            ((float4*)(out + OFF_RP))[i] = x;
        }
        return;
    }

    // ---- save_id gather + token append (single block) ----
    for (int i = threadIdx.x; i < BEAM * (HIST + 1); i += TPB) {
        int b = i / (HIST + 1);
        int j = i - b * (HIST + 1);
        int bi = g_beam_index[b];
        out[OFF_SAVE + i] = (j < HIST) ? (float)save_id[bi * HIST + j] : (float)g_token[b];
    }
}

// ---------------- launch ----------------
extern "C" void kernel_launch(void* const* d_in, const int* in_sizes, int n_in,
                              void* d_out, int out_size) {
    (void)in_sizes; (void)n_in; (void)out_size;

    const int*   save_id = (const int*)  d_in[16];
    const float* rpen    = (const float*)d_in[17];
    const float* prev    = (const float*)d_in[18];
    // d_in[19] = batch_indices (identity, unused)
    const float* logits  = (const float*)d_in[20];
    const float* pen     = (const float*)d_in[21];
    float* out = (float*)d_out;

    softmax_topk_kernel<<<dim3(SM_CHUNKS, BEAM), TPB_SM>>>(
        (const float4*)logits, (const float4*)rpen, prev,
        out + OFF_PROB, out + OFF_TOK, out + OFF_MAXIDX);

    KvPtrs kp;
    for (int i = 0; i < NUM_KV; i++) kp.p[i] = (const float4*)d_in[i];

    cudaFuncSetAttribute(gather_tma_kernel,
                         cudaFuncAttributeMaxDynamicSharedMemorySize, SMEM_BYTES);
    gather_tma_kernel<<<TOTAL_BLKS, TPB, SMEM_BYTES>>>(kp, rpen, save_id, pen, out);
}

// round 17
// speedup vs baseline: 1.1401x; 1.1401x over previous
#include <cuda_runtime.h>
#include <math.h>
#include <float.h>
#include <stdint.h>

// ---------------- problem constants ----------------
#define BEAM   5
#define TOPK   5
#define VOCAB  128000
#define HIST   511
#define NUM_KV 16
#define HEADS  8
#define SEQ    2048
#define HDIM   128

#define SM_CHUNKS 125
#define TPB_SM    256
#define NWARPS_B  (SM_CHUNKS*8)

#define NEG_SENTINEL (-FLT_MAX)

#define KV_ROW_ELEMS  (HEADS*SEQ*HDIM)          // 2,097,152 floats per (kv,beam)
#define KV_ROW4       (KV_ROW_ELEMS/4)
#define KV_ROW_BYTES  (KV_ROW_ELEMS*4)          // 8 MB
#define KV_TOTAL      (NUM_KV*BEAM*KV_ROW_ELEMS)

// output layout (floats), reference tuple order
#define OFF_SAVE   (KV_TOTAL)
#define OFF_RP     (OFF_SAVE + BEAM*(HIST+1))
#define OFF_PROB   (OFF_RP + BEAM*VOCAB)
#define OFF_TOK    (OFF_PROB + BEAM)
#define OFF_MAXIDX (OFF_TOK + BEAM)

// ---------------- device scratch ----------------
__device__ float g_wm[BEAM*NWARPS_B];
__device__ float g_ws[BEAM*NWARPS_B];
__device__ int   g_beam_index[BEAM];
__device__ int   g_token[BEAM];
__device__ unsigned int g_counter = 0;   // softmax ticket (reset by combine)
__device__ unsigned int g_work    = 0;   // gather work queue (reset by combine each run)

// ---------------- top-5 helpers ----------------
__device__ __forceinline__ void top5_insert(float* v, int* ix, float val, int idx) {
    if (val < v[TOPK-1]) return;
    if (val == v[TOPK-1] && idx >= ix[TOPK-1]) return;
    int p = TOPK - 1;
    #pragma unroll
    for (int q = TOPK - 1; q > 0; q--) {
        if (val > v[q-1] || (val == v[q-1] && idx < ix[q-1])) {
            v[q] = v[q-1]; ix[q] = ix[q-1]; p = q - 1;
        } else break;
    }
    v[p] = val; ix[p] = idx;
}

__device__ __forceinline__ void warp_merge(float* v, int* ix, float& m, float& s) {
    #pragma unroll
    for (int off = 16; off > 0; off >>= 1) {
        float pv[TOPK]; int pi[TOPK];
        #pragma unroll
        for (int j = 0; j < TOPK; j++) {
            pv[j] = __shfl_down_sync(0xffffffffu, v[j],  off);
            pi[j] = __shfl_down_sync(0xffffffffu, ix[j], off);
        }
        float pm = __shfl_down_sync(0xffffffffu, m, off);
        float ps = __shfl_down_sync(0xffffffffu, s, off);
        #pragma unroll
        for (int j = 0; j < TOPK; j++) top5_insert(v, ix, pv[j], pi[j]);
        float nm = fmaxf(m, pm);
        s = s * __expf(m - nm) + ps * __expf(pm - nm);
        m = nm;
    }
}

// ---------------- kernel 1: softmax/topk (R14; combine also resets g_work) ----------------
__global__ void __launch_bounds__(TPB_SM)
softmax_topk_kernel(const float4* __restrict__ logits, const float4* __restrict__ rpen,
                    const float* __restrict__ prev_prob,
                    float* __restrict__ out_prob,
                    float* __restrict__ out_tok,
                    float* __restrict__ out_maxidx) {
    const int c = blockIdx.x;
    const int b = blockIdx.y;
    const int t = threadIdx.x;
    const int warp = t >> 5;
    const int lane = t & 31;

    const int f4i = c * TPB_SM + t;
    float4 xl = __ldg(logits + (size_t)b * (VOCAB/4) + f4i);
    float4 xr = __ldg(rpen   + (size_t)b * (VOCAB/4) + f4i);
    float x0 = xl.x * xr.x, x1 = xl.y * xr.y, x2 = xl.z * xr.z, x3 = xl.w * xr.w;

    float m = fmaxf(fmaxf(x0, x1), fmaxf(x2, x3));
    float s = __expf(x0-m) + __expf(x1-m) + __expf(x2-m) + __expf(x3-m);

    #pragma unroll
    for (int off = 16; off > 0; off >>= 1) {
        float pm = __shfl_down_sync(0xffffffffu, m, off);
        float ps = __shfl_down_sync(0xffffffffu, s, off);
        float nm = fmaxf(m, pm);
        s = s * __expf(m - nm) + ps * __expf(pm - nm);
        m = nm;
    }
    if (lane == 0) {
        const int ws_idx = b * NWARPS_B + c * 8 + warp;
        g_wm[ws_idx] = m;
        g_ws[ws_idx] = s;
        __threadfence();
    }
    __syncthreads();

    __shared__ int s_last;
    if (t == 0) {
        unsigned int tk = atomicAdd(&g_counter, 1u);
        s_last = (tk == (unsigned)(SM_CHUNKS*BEAM - 1));
    }
    __syncthreads();
    if (!s_last) return;

    __shared__ float s_cur[BEAM*TOPK];
    __shared__ int   s_ctok[BEAM*TOPK];

    if (warp < BEAM) {
        const int bb = warp;
        float v[TOPK]; int ix[TOPK];
        #pragma unroll
        for (int j = 0; j < TOPK; j++) { v[j] = NEG_SENTINEL; ix[j] = 0x7FFFFFFF; }
        float cm = NEG_SENTINEL, cs = 0.0f;
        for (int i = lane; i < 1024; i += 32) {
            float pm = NEG_SENTINEL, ps = 0.0f;
            if (i < NWARPS_B) { pm = g_wm[bb*NWARPS_B + i]; ps = g_ws[bb*NWARPS_B + i]; }
            float nm = fmaxf(cm, pm);
            cs = cs * __expf(cm - nm) + ps * __expf(pm - nm);
            cm = nm;
            top5_insert(v, ix, pm, i);
        }
        warp_merge(v, ix, cm, cs);

        float lse = cm + logf(cs);
        lse = __shfl_sync(0xffffffffu, lse, 0);
        int slots[TOPK];
        #pragma unroll
        for (int j = 0; j < TOPK; j++) slots[j] = __shfl_sync(0xffffffffu, ix[j], 0);

        float tv[TOPK]; int ti[TOPK];
        #pragma unroll
        for (int j = 0; j < TOPK; j++) { tv[j] = NEG_SENTINEL; ti[j] = 0x7FFFFFFF; }
        #pragma unroll
        for (int j = 0; j < TOPK; j++) {
            const int ws = slots[j];
            const int f4 = ws * 32 + lane;
            float4 yl = __ldg(logits + (size_t)bb * (VOCAB/4) + f4);
            float4 yr = __ldg(rpen   + (size_t)bb * (VOCAB/4) + f4);
            const int e0 = f4 * 4;
            top5_insert(tv, ti, yl.x * yr.x, e0 + 0);
            top5_insert(tv, ti, yl.y * yr.y, e0 + 1);
            top5_insert(tv, ti, yl.z * yr.z, e0 + 2);
            top5_insert(tv, ti, yl.w * yr.w, e0 + 3);
        }
        float dm = NEG_SENTINEL, ds = 0.0f;
        warp_merge(tv, ti, dm, ds);

        if (lane == 0) {
            float pp = prev_prob[bb];
            #pragma unroll
            for (int j = 0; j < TOPK; j++) {
                s_cur[bb*TOPK + j]  = tv[j] - lse + pp;
                s_ctok[bb*TOPK + j] = ti[j];
            }
        }
    }
    __syncthreads();

    if (t == 0) {
        bool used[BEAM*TOPK];
        #pragma unroll
        for (int i = 0; i < BEAM*TOPK; i++) used[i] = false;
        for (int k = 0; k < BEAM; k++) {
            int best = 0; float bv = -INFINITY;
            for (int i = 0; i < BEAM*TOPK; i++) {
                if (!used[i] && s_cur[i] > bv) { bv = s_cur[i]; best = i; }
            }
            used[best] = true;
            int bi  = best / TOPK;
            int tok = s_ctok[best];
            g_beam_index[k] = bi;
            g_token[k]      = tok;
            out_prob[k]     = bv;
            out_tok[k]      = (float)tok;
            if (k == 0) out_maxidx[0] = (float)tok;
        }
        g_counter = 0;
        g_work    = 0;                   // reset gather work queue for this run
        __threadfence();
    }
}

// ---------------- kernel 2: persistent work-queue TMA gather ----------------
// 148 driver blocks (1 wave, 1 CTA/SM @192KB smem). Thread 0 runs a 3x64KB
// lookahead-2 TMA pipeline fed by a global atomic queue of 64KB chunks
// (80 rows x 128 chunks; inactive-source items skipped) -> perfect balance,
// one ramp per SM, reads = unique_beams*128MB structurally.
// Threads 1..127 concurrently do this block's slice of rp (+save in block 0).
struct KvPtrs { const float4* p[NUM_KV]; };

#define TPB         128
#define CHUNK       65536
#define NBUF        3
#define CH_PER_ROW  (KV_ROW_BYTES/CHUNK)            // 128
#define TOTAL_ITEMS (NUM_KV*BEAM*CH_PER_ROW)        // 10240
#define NBLK        148
#define RP_F4       (BEAM*VOCAB/4)                  // 160000
#define RP_PER_BLK  ((RP_F4 + NBLK - 1)/NBLK)       // 1082
#define SMEM_BYTES  (NBUF*CHUNK + 32)

__device__ __forceinline__ uint32_t smem_u32(const void* p) {
    uint32_t a;
    asm("{ .reg .u64 t; cvta.to.shared.u64 t, %1; cvt.u32.u64 %0, t; }" : "=r"(a) : "l"(p));
    return a;
}

__device__ __forceinline__ void mbar_wait(uint32_t mb, uint32_t parity) {
    uint32_t done;
    asm volatile(
        "{\n\t.reg .pred p;\n\t"
        "mbarrier.try_wait.parity.acquire.cta.shared::cta.b64 p, [%1], %2;\n\t"
        "selp.b32 %0, 1, 0, p;\n\t}"
        : "=r"(done) : "r"(mb), "r"(parity) : "memory");
    while (!done) {
        asm volatile(
            "{\n\t.reg .pred p;\n\t"
            "mbarrier.try_wait.parity.acquire.cta.shared::cta.b64 p, [%1], %2, 0x989680;\n\t"
            "selp.b32 %0, 1, 0, p;\n\t}"
            : "=r"(done) : "r"(mb), "r"(parity) : "memory");
    }
}

__device__ __forceinline__ void tma_load(uint32_t buf, const char* src, uint32_t mb) {
    asm volatile("mbarrier.arrive.expect_tx.shared.b64 _, [%0], %1;"
                 :: "r"(mb), "r"((uint32_t)CHUNK) : "memory");
    asm volatile(
        "cp.async.bulk.shared::cluster.global.mbarrier::complete_tx::bytes "
        "[%0], [%1], %2, [%3];"
        :: "r"(buf), "l"(src), "r"((uint32_t)CHUNK), "r"(mb) : "memory");
}

// next ACTIVE work item (chunk index), or -1 when queue drained
__device__ __forceinline__ int grab(const int* smask) {
    for (;;) {
        unsigned int n = atomicAdd(&g_work, 1u);
        if (n >= (unsigned)TOTAL_ITEMS) return -1;
        int row = (int)(n >> 7);            // / CH_PER_ROW
        if (smask[row % BEAM]) return (int)n;
    }
}

__global__ void __launch_bounds__(TPB)
gather_tma_kernel(KvPtrs kp,
                  const float* __restrict__ rpen,
                  const int*   __restrict__ save_id,
                  const float* __restrict__ pen,
                  float* __restrict__ out) {
    extern __shared__ char smem[];
    const int t = threadIdx.x;

    if (t != 0) {
        // ---- threads 1..127: rp slice (+save in block 0), concurrent with TMA ----
        const int base = blockIdx.x * RP_PER_BLK;
        const int cnt  = min(RP_PER_BLK, RP_F4 - base);
        for (int k = t - 1; k < cnt; k += TPB - 1) {
            int i  = base + k;
            int b  = i / (VOCAB/4);
            int v4 = i - b * (VOCAB/4);
            int bi = g_beam_index[b];
            float4 x = __ldcg((const float4*)rpen + (size_t)bi * (VOCAB/4) + v4);
            int tok = g_token[b];
            if ((tok >> 2) == v4) {
                float p = pen[0];
                ((float*)&x)[tok & 3] *= p;
            }
            ((float4*)(out + OFF_RP))[i] = x;
        }
        if (blockIdx.x == 0) {
            for (int i = t - 1; i < BEAM * (HIST + 1); i += TPB - 1) {
                int b = i / (HIST + 1);
                int j = i - b * (HIST + 1);
                int bi = g_beam_index[b];
                out[OFF_SAVE + i] = (j < HIST) ? (float)save_id[bi * HIST + j]
                                               : (float)g_token[b];
            }
        }
        return;
    }

    // ---- thread 0: persistent TMA driver ----
    int bi[BEAM], smask[BEAM];
    #pragma unroll
    for (int d = 0; d < BEAM; d++) bi[d] = g_beam_index[d];
    #pragma unroll
    for (int si = 0; si < BEAM; si++) {
        int msk = 0;
        #pragma unroll
        for (int d = 0; d < BEAM; d++)
            if (bi[d] == si) msk |= (1 << d);
        smask[si] = msk;
    }

    const uint32_t buf0 = smem_u32(smem);
    const uint32_t mbar = buf0 + NBUF*CHUNK;
    #pragma unroll
    for (int i = 0; i < NBUF; i++)
        asm volatile("mbarrier.init.shared.b64 [%0], 1;" :: "r"(mbar + 8*i) : "memory");
    asm volatile("fence.proxy.async.shared::cta;" ::: "memory");

    char* outb = (char*)out;
    uint32_t ph[NBUF];
    int      it[NBUF];
    #pragma unroll
    for (int i = 0; i < NBUF; i++) ph[i] = 0;

    // prefill: lookahead 2
    int c_issued = 0;
    #pragma unroll
    for (int k = 0; k < 2; k++) {
        int item = grab(smask);
        if (item < 0) break;
        int row = item >> 7, ch = item & (CH_PER_ROW - 1);
        int kv = row / BEAM, si = row % BEAM;
        const char* src = (const char*)kp.p[kv] + (size_t)si * KV_ROW_BYTES
                                                + (size_t)ch * CHUNK;
        it[c_issued % NBUF] = item;
        tma_load(buf0 + (c_issued % NBUF) * CHUNK, src, mbar + 8*(c_issued % NBUF));
        c_issued++;
    }

    for (int c = 0; c < c_issued; c++) {
        const int s = c % NBUF;
        const uint32_t buf = buf0 + s * CHUNK;

        mbar_wait(mbar + 8*s, ph[s]);
        ph[s] ^= 1;

        const int item = it[s];
        const int row = item >> 7, ch = item & (CH_PER_ROW - 1);
        const int kv = row / BEAM, si = row % BEAM;
        const int msk = smask[si];

        #pragma unroll
        for (int d = 0; d < BEAM; d++) {
            if (msk & (1 << d)) {
                char* dst = outb + ((size_t)kv * BEAM + d) * KV_ROW_BYTES
                                 + (size_t)ch * CHUNK;
                asm volatile(
                    "cp.async.bulk.global.shared::cta.bulk_group [%0], [%1], %2;"
                    :: "l"(dst), "r"(buf), "r"((uint32_t)CHUNK) : "memory");
            }
        }
        asm volatile("cp.async.bulk.commit_group;" ::: "memory");

        if (c_issued == c + 2) {                 // maintain lookahead 2
            int item2 = grab(smask);
            if (item2 >= 0) {
                // store-group (c-1) must be done reading buf[(c+2)%NBUF]
                asm volatile("cp.async.bulk.wait_group.read 1;" ::: "memory");
                int row2 = item2 >> 7, ch2 = item2 & (CH_PER_ROW - 1);
                int kv2 = row2 / BEAM, si2 = row2 % BEAM;
                const char* src2 = (const char*)kp.p[kv2] + (size_t)si2 * KV_ROW_BYTES
                                                          + (size_t)ch2 * CHUNK;
                const int j = (c + 2) % NBUF;
                it[j] = item2;
                tma_load(buf0 + j * CHUNK, src2, mbar + 8*j);
                c_issued++;
            }
        }
    }
    asm volatile("cp.async.bulk.wait_group 0;" ::: "memory");
}

// ---------------- launch ----------------
extern "C" void kernel_launch(void* const* d_in, const int* in_sizes, int n_in,
                              void* d_out, int out_size) {
    (void)in_sizes; (void)n_in; (void)out_size;

    const int*   save_id = (const int*)  d_in[16];
    const float* rpen    = (const float*)d_in[17];
    const float* prev    = (const float*)d_in[18];
    // d_in[19] = batch_indices (identity, unused)
    const float* logits  = (const float*)d_in[20];
    const float* pen     = (const float*)d_in[21];
    float* out = (float*)d_out;

    softmax_topk_kernel<<<dim3(SM_CHUNKS, BEAM), TPB_SM>>>(
        (const float4*)logits, (const float4*)rpen, prev,
        out + OFF_PROB, out + OFF_TOK, out + OFF_MAXIDX);

    KvPtrs kp;
    for (int i = 0; i < NUM_KV; i++) kp.p[i] = (const float4*)d_in[i];

    cudaFuncSetAttribute(gather_tma_kernel,
                         cudaFuncAttributeMaxDynamicSharedMemorySize, SMEM_BYTES);
    gather_tma_kernel<<<NBLK, TPB, SMEM_BYTES>>>(kp, rpen, save_id, pen, out);
}